// round 12
// baseline (speedup 1.0000x reference)
#include <cuda_runtime.h>
#include <cuda_bf16.h>

#define NFFT     4096
#define NTH      256
#define BATCH    32
#define NA_      256
#define LOUT     2048
#define SPAD     4352   // 4096 + 4096/16 padding

#define NX_ELEMS    (BATCH * LOUT)        // 65536
#define NPSIH_ELEMS (NA_ * NFFT)          // 1048576
#define NCPLX       (BATCH * NA_ * LOUT)  // 16,777,216 complex output values

struct cplx { float x, y; };

__device__ __forceinline__ cplx cmul(cplx a, cplx b) {
    return cplx{fmaf(a.x, b.x, -a.y * b.y), fmaf(a.x, b.y, a.y * b.x)};
}

// multiply by DIR * i
template<int DIR>
__device__ __forceinline__ cplx muli(cplx a) {
    return (DIR > 0) ? cplx{-a.y, a.x} : cplx{a.y, -a.x};
}

// radix-4 butterfly, in place
template<int DIR>
__device__ __forceinline__ void bfly4(cplx& a, cplx& b, cplx& c, cplx& d) {
    cplx s0{a.x + c.x, a.y + c.y}, d0{a.x - c.x, a.y - c.y};
    cplx s1{b.x + d.x, b.y + d.y}, d1{b.x - d.x, b.y - d.y};
    cplx id1 = muli<DIR>(d1);
    a = cplx{s0.x + s1.x, s0.y + s1.y};
    b = cplx{d0.x + id1.x, d0.y + id1.y};
    c = cplx{s0.x - s1.x, s0.y - s1.y};
    d = cplx{d0.x - id1.x, d0.y - id1.y};
}

#define C16 0.92387953251128675f
#define S16 0.38268343236508977f
#define RS2 0.70710678118654752f

// internal W16^{n0*k0} twiddles; value A[n0][k0] lives at v[n0 + 4*k0].
template<int DIR>
__device__ __forceinline__ void mid_twiddle(cplx v[16]) {
    const float d = (DIR > 0) ? 1.f : -1.f;
    v[5]  = cmul(v[5],  cplx{ C16,  d * S16});   // W^1
    v[9]  = cmul(v[9],  cplx{ RS2,  d * RS2});   // W^2
    v[13] = cmul(v[13], cplx{ S16,  d * C16});   // W^3
    v[6]  = cmul(v[6],  cplx{ RS2,  d * RS2});   // W^2
    v[10] = muli<DIR>(v[10]);                    // W^4
    v[14] = cmul(v[14], cplx{-RS2,  d * RS2});   // W^6
    v[7]  = cmul(v[7],  cplx{ S16,  d * C16});   // W^3
    v[11] = cmul(v[11], cplx{-RS2,  d * RS2});   // W^6
    v[15] = cmul(v[15], cplx{-C16, -d * S16});   // W^9
}

template<int DIR>
__device__ __forceinline__ void layer1(cplx v[16]) {
    #pragma unroll
    for (int n0 = 0; n0 < 4; n0++)
        bfly4<DIR>(v[n0], v[n0 + 4], v[n0 + 8], v[n0 + 12]);
}

template<int DIR>
__device__ __forceinline__ void layer2(cplx v[16]) {
    #pragma unroll
    for (int k0 = 0; k0 < 4; k0++)
        bfly4<DIR>(v[4 * k0], v[4 * k0 + 1], v[4 * k0 + 2], v[4 * k0 + 3]);
}

template<int DIR>
__device__ __forceinline__ void dft16(cplx v[16]) {
    layer1<DIR>(v);
    mid_twiddle<DIR>(v);
    layer2<DIR>(v);
}

// v[q] *= w1^q, powers by multiply chain
template<int DIR>
__device__ __forceinline__ void twiddle_chain(cplx v[16], cplx w1) {
    cplx w = w1;
    #pragma unroll
    for (int q = 1; q < 16; q++) {
        v[q] = cmul(v[q], w);
        if (q < 15) w = cmul(w, w1);
    }
}

__device__ __forceinline__ int sp(int i) { return i + (i >> 4); }  // bank-pad
__device__ __forceinline__ int REV(int q) { return ((q & 3) << 2) | (q >> 2); }

// ---------------- device scratch (no allocations allowed) ----------------
__device__ float2 d_tw[NFFT];            // exp(+2*pi*i*k/NFFT)
__device__ float2 d_xh[BATCH * NFFT];    // forward FFT of padded input

// ---------------- kernel 0: twiddle table ----------------
__global__ void k_twiddle() {
    int k = blockIdx.x * blockDim.x + threadIdx.x;
    float s, c;
    sincospif((float)k * (2.0f / NFFT), &s, &c);
    d_tw[k] = make_float2(c, s);
}

// ---------------- kernel 1: forward FFT of reflect-padded x ----------------
__global__ void __launch_bounds__(NTH) k_fwd(const float* __restrict__ x) {
    __shared__ float2 S[SPAD];
    const int t = threadIdx.x, b = blockIdx.x;
    cplx v[16];

    // stage 1 (Ns=1): reflect-padded gather, clamped
    #pragma unroll
    for (int q = 0; q < 16; q++) {
        int i = t + q * 256;
        int s = (i < 1024) ? (1024 - i) : ((i < 3072) ? (i - 1024) : (5118 - i));
        int g = b * LOUT + s;
        g = (g < NX_ELEMS) ? g : (NX_ELEMS - 1);   // never fires if shapes match
        v[q] = cplx{x[g], 0.f};
    }
    dft16<-1>(v);
    #pragma unroll
    for (int q = 0; q < 16; q++) {
        cplx r = v[REV(q)];
        S[sp(t * 16 + q)] = make_float2(r.x, r.y);
    }
    __syncthreads();

    // stage 2 (Ns=16)
    #pragma unroll
    for (int q = 0; q < 16; q++) {
        float2 f = S[sp(t + q * 256)];
        v[q] = cplx{f.x, f.y};
    }
    __syncthreads();
    {
        float2 w = d_tw[16 * (t & 15)];
        twiddle_chain<-1>(v, cplx{w.x, -w.y});   // forward: conj
    }
    dft16<-1>(v);
    {
        int idxD = (t >> 4) * 256 + (t & 15);
        #pragma unroll
        for (int q = 0; q < 16; q++) {
            cplx r = v[REV(q)];
            S[sp(idxD + q * 16)] = make_float2(r.x, r.y);
        }
    }
    __syncthreads();

    // stage 3 (Ns=256): write spectrum to scratch
    #pragma unroll
    for (int q = 0; q < 16; q++) {
        float2 f = S[sp(t + q * 256)];
        v[q] = cplx{f.x, f.y};
    }
    {
        float2 w = d_tw[t];
        twiddle_chain<-1>(v, cplx{w.x, -w.y});
    }
    dft16<-1>(v);
    #pragma unroll
    for (int q = 0; q < 16; q++) {
        cplx r = v[REV(q)];
        d_xh[b * NFFT + t + q * 256] = make_float2(r.x, r.y);
    }
}

// ---------------- kernel 2: Psih multiply + 4096-pt IFFT + crop ----------------
// REAL_ONLY = true  -> out is float32 (B, NA, L): store Re only (need floats).
// REAL_ONLY = false -> out is float32 (B, NA, L, 2) / complex64: store pairs.
template<bool REAL_ONLY>
__global__ void __launch_bounds__(NTH) k_cwt(const float* __restrict__ Psih,
                                             float* __restrict__ outf) {
    __shared__ float2 S[SPAD];
    const int t = threadIdx.x;
    const int a = blockIdx.x, b = blockIdx.y;
    const float2* xh = d_xh + (size_t)b * NFFT;
    cplx v[16];
    const float inv = 1.0f / NFFT;

    // ---- stage 1 (Ns=1), fused with filter multiply.
    // Psih is analytic: bins k>=2048 (and k=0) are zero -> v[8..15] == 0.
    #pragma unroll
    for (int q = 0; q < 8; q++) {
        int k = t + q * 256;
        int g = a * NFFT + k;
        g = (g < NPSIH_ELEMS) ? g : (NPSIH_ELEMS - 1);  // never fires if shapes match
        float2 h = xh[k];
        float p = Psih[g] * inv;
        v[q] = cplx{h.x * p, h.y * p};
    }
    // half-zero radix-4 layer 1: (A, B, 0, 0)
    #pragma unroll
    for (int n0 = 0; n0 < 4; n0++) {
        cplx A = v[n0], B = v[n0 + 4];
        cplx iB = muli<1>(B);
        v[n0]      = cplx{A.x + B.x,  A.y + B.y};
        v[n0 + 4]  = cplx{A.x + iB.x, A.y + iB.y};
        v[n0 + 8]  = cplx{A.x - B.x,  A.y - B.y};
        v[n0 + 12] = cplx{A.x - iB.x, A.y - iB.y};
    }
    mid_twiddle<1>(v);
    layer2<1>(v);
    #pragma unroll
    for (int q = 0; q < 16; q++) {
        cplx r = v[REV(q)];
        S[sp(t * 16 + q)] = make_float2(r.x, r.y);
    }
    __syncthreads();

    // ---- stage 2 (Ns=16)
    #pragma unroll
    for (int q = 0; q < 16; q++) {
        float2 f = S[sp(t + q * 256)];
        v[q] = cplx{f.x, f.y};
    }
    __syncthreads();
    {
        float2 w = d_tw[16 * (t & 15)];
        twiddle_chain<1>(v, cplx{w.x, w.y});
    }
    dft16<1>(v);
    {
        int idxD = (t >> 4) * 256 + (t & 15);
        #pragma unroll
        for (int q = 0; q < 16; q++) {
            cplx r = v[REV(q)];
            S[sp(idxD + q * 16)] = make_float2(r.x, r.y);
        }
    }
    __syncthreads();

    // ---- stage 3 (Ns=256), fused with cropped output.
    // Output n = t + q*256; crop keeps n in [1024,3072) -> only k1 = 1,2
    // quarters of the final radix-4 layer are materialized.
    #pragma unroll
    for (int q = 0; q < 16; q++) {
        float2 f = S[sp(t + q * 256)];
        v[q] = cplx{f.x, f.y};
    }
    {
        float2 w = d_tw[t];
        twiddle_chain<1>(v, cplx{w.x, w.y});
    }
    layer1<1>(v);
    mid_twiddle<1>(v);

    const size_t base = (size_t)(b * NA_ + a) * LOUT;   // complex-element index
    #pragma unroll
    for (int k0 = 0; k0 < 4; k0++) {
        cplx e0 = v[4 * k0], e1 = v[4 * k0 + 1], e2 = v[4 * k0 + 2], e3 = v[4 * k0 + 3];
        // X[k0+4] = (e0-e2) + i*(e1-e3) ; X[k0+8] = (e0+e2) - (e1+e3)
        cplx dm{e0.x - e2.x, e0.y - e2.y};
        cplx dn{e1.x - e3.x, e1.y - e3.y};
        cplx idn = muli<1>(dn);
        float2 X4 = make_float2(dm.x + idn.x, dm.y + idn.y);
        float2 X8 = make_float2(e0.x + e2.x - e1.x - e3.x,
                                e0.y + e2.y - e1.y - e3.y);
        size_t i4 = base + t + k0 * 256;         // n = t + (k0+4)*256
        size_t i8 = base + t + (k0 + 4) * 256;   // n = t + (k0+8)*256
        if (REAL_ONLY) {
            // max byte touched: (NCPLX-1)*4 + 4 = 64 MB  (buffer >= NCPLX floats)
            outf[i4] = X4.x;
            outf[i8] = X8.x;
        } else {
            // max byte touched: (NCPLX-1)*8 + 8 = 128 MB (buffer >= 2*NCPLX floats)
            reinterpret_cast<float2*>(outf)[i4] = X4;
            reinterpret_cast<float2*>(outf)[i8] = X8;
        }
    }
}

// ---------------- launcher ----------------
extern "C" void kernel_launch(void* const* d_in, const int* in_sizes, int n_in,
                              void* d_out, int out_size) {
    // Bind inputs by RELATIVE size — robust to ordering and to element/byte
    // units (x is the smaller buffer in any unit).
    int ix = 0, ip = 1;
    if (n_in >= 2 && in_sizes[0] > in_sizes[1]) { ix = 1; ip = 0; }
    const float* x    = (const float*)d_in[ix];
    const float* Psih = (const float*)d_in[ip];

    k_twiddle<<<NFFT / NTH, NTH>>>();
    k_fwd<<<BATCH, NTH>>>(x);

    // Output layout from out_size (documented as ELEMENT count of __output__):
    //   >= 2*NCPLX  -> float32 (..., 2) interleaved (or byte count): full pairs.
    //   otherwise   -> float32 real-part only (complex64 -> float32 cast):
    //                  writing pairs would overrun a NCPLX-float buffer, which
    //                  matches the illegal-access signature of rounds 5-9.
    if ((long long)out_size >= 2LL * NCPLX) {
        k_cwt<false><<<dim3(NA_, BATCH), NTH>>>(Psih, (float*)d_out);
    } else {
        k_cwt<true><<<dim3(NA_, BATCH), NTH>>>(Psih, (float*)d_out);
    }
}

// round 13
// speedup vs baseline: 1.0537x; 1.0537x over previous
#include <cuda_runtime.h>
#include <cuda_bf16.h>

#define NFFT     4096
#define NTH      256
#define BATCH    32
#define NA_      256
#define LOUT     2048
#define SPAD     4352   // 4096 + 4096/16 padding

#define NCPLX    (BATCH * NA_ * LOUT)  // 16,777,216 complex output values

// ---------------- packed complex: one complex64 in a 64-bit f32x2 ----------------
typedef unsigned long long u64c;

__device__ __forceinline__ u64c pk(float x, float y) {
    u64c r; asm("mov.b64 %0,{%1,%2};" : "=l"(r) : "f"(x), "f"(y)); return r;
}
__device__ __forceinline__ void upk(u64c v, float& x, float& y) {
    asm("mov.b64 {%0,%1},%2;" : "=f"(x), "=f"(y) : "l"(v));
}
__device__ __forceinline__ u64c padd(u64c a, u64c b) {
    u64c r; asm("add.rn.f32x2 %0,%1,%2;" : "=l"(r) : "l"(a), "l"(b)); return r;
}
__device__ __forceinline__ u64c pmul(u64c a, u64c b) {
    u64c r; asm("mul.rn.f32x2 %0,%1,%2;" : "=l"(r) : "l"(a), "l"(b)); return r;
}
__device__ __forceinline__ u64c pfma(u64c a, u64c b, u64c c) {
    u64c r; asm("fma.rn.f32x2 %0,%1,%2,%3;" : "=l"(r) : "l"(a), "l"(b), "l"(c)); return r;
}
// a - b  ==  fma(b, {-1,-1}, a)   (sub.f32x2 availability uncertain; fma is proven)
__device__ __forceinline__ u64c psub(u64c a, u64c b) {
    return pfma(b, pk(-1.f, -1.f), a);
}
__device__ __forceinline__ float negf(float a) {
    return __int_as_float(__float_as_int(a) ^ 0x80000000u);  // LOP3, alu pipe
}
// multiply by DIR * i:  +i*(x,y) = (-y, x) ;  -i*(x,y) = (y, -x)
template<int DIR>
__device__ __forceinline__ u64c pmuli(u64c a) {
    float x, y; upk(a, x, y);
    return (DIR > 0) ? pk(negf(y), x) : pk(y, negf(x));
}
// complex multiply by scalar-held twiddle (wx, wy)
__device__ __forceinline__ u64c pcmulw(u64c a, float wx, float wy) {
    float x, y; upk(a, x, y);
    return pk(fmaf(x, wx, -(y * wy)), fmaf(x, wy, y * wx));
}

// radix-4 butterfly, packed, in place
template<int DIR>
__device__ __forceinline__ void pbfly4(u64c& a, u64c& b, u64c& c, u64c& d) {
    u64c s0 = padd(a, c), d0 = psub(a, c);
    u64c s1 = padd(b, d), d1 = psub(b, d);
    u64c id1 = pmuli<DIR>(d1);
    a = padd(s0, s1); b = padd(d0, id1);
    c = psub(s0, s1); d = psub(d0, id1);
}

#define C16 0.92387953251128675f
#define S16 0.38268343236508977f
#define RS2 0.70710678118654752f

// internal W16^{n0*k0} twiddles; value A[n0][k0] lives at v[n0 + 4*k0].
template<int DIR>
__device__ __forceinline__ void mid_twiddle(u64c v[16]) {
    const float d = (DIR > 0) ? 1.f : -1.f;
    v[5]  = pcmulw(v[5],   C16,  d * S16);   // W^1
    v[9]  = pcmulw(v[9],   RS2,  d * RS2);   // W^2
    v[13] = pcmulw(v[13],  S16,  d * C16);   // W^3
    v[6]  = pcmulw(v[6],   RS2,  d * RS2);   // W^2
    v[10] = pmuli<DIR>(v[10]);               // W^4
    v[14] = pcmulw(v[14], -RS2,  d * RS2);   // W^6
    v[7]  = pcmulw(v[7],   S16,  d * C16);   // W^3
    v[11] = pcmulw(v[11], -RS2,  d * RS2);   // W^6
    v[15] = pcmulw(v[15], -C16, -d * S16);   // W^9
}

template<int DIR>
__device__ __forceinline__ void layer1(u64c v[16]) {
    #pragma unroll
    for (int n0 = 0; n0 < 4; n0++)
        pbfly4<DIR>(v[n0], v[n0 + 4], v[n0 + 8], v[n0 + 12]);
}

template<int DIR>
__device__ __forceinline__ void layer2(u64c v[16]) {
    #pragma unroll
    for (int k0 = 0; k0 < 4; k0++)
        pbfly4<DIR>(v[4 * k0], v[4 * k0 + 1], v[4 * k0 + 2], v[4 * k0 + 3]);
}

template<int DIR>
__device__ __forceinline__ void dft16(u64c v[16]) {
    layer1<DIR>(v);
    mid_twiddle<DIR>(v);
    layer2<DIR>(v);
}

// v[q] *= w1^q; w maintained as scalar pair (chain of scalar FFMAs interleaves
// with the packed-apply's mov/alu ops on the other pipe)
__device__ __forceinline__ void ptwiddle_chain(u64c v[16], float w1x, float w1y) {
    float wx = w1x, wy = w1y;
    #pragma unroll
    for (int q = 1; q < 16; q++) {
        v[q] = pcmulw(v[q], wx, wy);
        if (q < 15) {
            float nx = fmaf(wx, w1x, -(wy * w1y));
            float ny = fmaf(wx, w1y, wy * w1x);
            wx = nx; wy = ny;
        }
    }
}

__device__ __forceinline__ int sp(int i) { return i + (i >> 4); }  // bank-pad
__device__ __forceinline__ int REV(int q) { return ((q & 3) << 2) | (q >> 2); }

// ---------------- device scratch (no allocations allowed) ----------------
__device__ float2 d_tw[NFFT];          // exp(+2*pi*i*k/NFFT)
__device__ u64c   d_xh[BATCH * NFFT];  // forward FFT of padded input, pre-scaled by 1/N

// ---------------- kernel 1: twiddle table + forward FFT of reflect-padded x ----
__global__ void __launch_bounds__(NTH) k_fwd(const float* __restrict__ x) {
    __shared__ u64c S[SPAD];
    const int t = threadIdx.x, b = blockIdx.x;
    u64c v[16];

    // Every CTA (re)writes the FULL twiddle table (benign duplicate writes of
    // identical values); __syncthreads makes own-CTA writes visible for use below.
    #pragma unroll
    for (int q = 0; q < 16; q++) {
        int k = t + q * 256;
        float s, c;
        sincospif((float)k * (2.0f / NFFT), &s, &c);
        d_tw[k] = make_float2(c, s);
    }
    __syncthreads();

    // stage 1 (Ns=1): reflect-padded gather
    #pragma unroll
    for (int q = 0; q < 16; q++) {
        int i = t + q * 256;
        int s = (i < 1024) ? (1024 - i) : ((i < 3072) ? (i - 1024) : (5118 - i));
        v[q] = pk(x[b * LOUT + s], 0.f);
    }
    dft16<-1>(v);
    #pragma unroll
    for (int q = 0; q < 16; q++) S[sp(t * 16 + q)] = v[REV(q)];
    __syncthreads();

    // stage 2 (Ns=16)
    #pragma unroll
    for (int q = 0; q < 16; q++) v[q] = S[sp(t + q * 256)];
    __syncthreads();
    {
        float2 w = d_tw[16 * (t & 15)];
        ptwiddle_chain(v, w.x, -w.y);   // forward: conjugate twiddles
    }
    dft16<-1>(v);
    {
        int idxD = (t >> 4) * 256 + (t & 15);
        #pragma unroll
        for (int q = 0; q < 16; q++) S[sp(idxD + q * 16)] = v[REV(q)];
    }
    __syncthreads();

    // stage 3 (Ns=256): write spectrum (pre-scaled by 1/N) to scratch
    #pragma unroll
    for (int q = 0; q < 16; q++) v[q] = S[sp(t + q * 256)];
    {
        float2 w = d_tw[t];
        ptwiddle_chain(v, w.x, -w.y);
    }
    dft16<-1>(v);
    const u64c invp = pk(1.0f / NFFT, 1.0f / NFFT);
    #pragma unroll
    for (int q = 0; q < 16; q++)
        d_xh[b * NFFT + t + q * 256] = pmul(v[REV(q)], invp);
}

// ---------------- kernel 2: Psih multiply + 4096-pt IFFT + crop ----------------
// REAL_ONLY = true  -> out is float32 (B, NA, L): store Re only.
// REAL_ONLY = false -> out is float32 (B, NA, L, 2) / complex64: store pairs.
template<bool REAL_ONLY>
__global__ void __launch_bounds__(NTH) k_cwt(const float* __restrict__ Psih,
                                             float* __restrict__ outf) {
    __shared__ u64c S[SPAD];
    const int t = threadIdx.x;
    const int a = blockIdx.x, b = blockIdx.y;
    const u64c* xh = d_xh + (size_t)b * NFFT;
    const float* P = Psih + (size_t)a * NFFT;
    u64c v[16];

    // ---- stage 1 (Ns=1), fused with filter multiply.
    // Psih is analytic: bins k>=2048 (and k=0) are zero -> v[8..15] == 0.
    #pragma unroll
    for (int q = 0; q < 8; q++) {
        int k = t + q * 256;
        float p = P[k];                 // spectrum already carries the 1/N
        v[q] = pmul(xh[k], pk(p, p));
    }
    // half-zero radix-4 layer 1: (A, B, 0, 0)
    #pragma unroll
    for (int n0 = 0; n0 < 4; n0++) {
        u64c A = v[n0], B = v[n0 + 4];
        u64c iB = pmuli<1>(B);
        v[n0]      = padd(A, B);
        v[n0 + 4]  = padd(A, iB);
        v[n0 + 8]  = psub(A, B);
        v[n0 + 12] = psub(A, iB);
    }
    mid_twiddle<1>(v);
    layer2<1>(v);
    #pragma unroll
    for (int q = 0; q < 16; q++) S[sp(t * 16 + q)] = v[REV(q)];
    __syncthreads();

    // ---- stage 2 (Ns=16)
    #pragma unroll
    for (int q = 0; q < 16; q++) v[q] = S[sp(t + q * 256)];
    __syncthreads();
    {
        float2 w = d_tw[16 * (t & 15)];
        ptwiddle_chain(v, w.x, w.y);
    }
    dft16<1>(v);
    {
        int idxD = (t >> 4) * 256 + (t & 15);
        #pragma unroll
        for (int q = 0; q < 16; q++) S[sp(idxD + q * 16)] = v[REV(q)];
    }
    __syncthreads();

    // ---- stage 3 (Ns=256), fused with cropped output.
    // Output n = t + q*256; crop keeps n in [1024,3072) -> only the k1=1,2
    // quarters of the final radix-4 layer are materialized.
    #pragma unroll
    for (int q = 0; q < 16; q++) v[q] = S[sp(t + q * 256)];
    {
        float2 w = d_tw[t];
        ptwiddle_chain(v, w.x, w.y);
    }
    layer1<1>(v);
    mid_twiddle<1>(v);

    const size_t base = (size_t)(b * NA_ + a) * LOUT;   // complex-element index
    #pragma unroll
    for (int k0 = 0; k0 < 4; k0++) {
        u64c e0 = v[4 * k0], e1 = v[4 * k0 + 1], e2 = v[4 * k0 + 2], e3 = v[4 * k0 + 3];
        // X[k0+4] = (e0-e2) + i*(e1-e3) ; X[k0+8] = (e0+e2) - (e1+e3)
        u64c dm  = psub(e0, e2);
        u64c dn  = psub(e1, e3);
        u64c X4  = padd(dm, pmuli<1>(dn));
        u64c X8  = psub(padd(e0, e2), padd(e1, e3));
        size_t i4 = base + t + k0 * 256;         // n = t + (k0+4)*256
        size_t i8 = base + t + (k0 + 4) * 256;   // n = t + (k0+8)*256
        if (REAL_ONLY) {
            float xr, xi;
            upk(X4, xr, xi); outf[i4] = xr;
            upk(X8, xr, xi); outf[i8] = xr;
        } else {
            reinterpret_cast<u64c*>(outf)[i4] = X4;
            reinterpret_cast<u64c*>(outf)[i8] = X8;
        }
    }
}

// ---------------- launcher ----------------
extern "C" void kernel_launch(void* const* d_in, const int* in_sizes, int n_in,
                              void* d_out, int out_size) {
    // Bind inputs by RELATIVE size (x is the smaller buffer in any unit).
    int ix = 0, ip = 1;
    if (n_in >= 2 && in_sizes[0] > in_sizes[1]) { ix = 1; ip = 0; }
    const float* x    = (const float*)d_in[ix];
    const float* Psih = (const float*)d_in[ip];

    k_fwd<<<BATCH, NTH>>>(x);

    // Output layout from out_size: >= 2*NCPLX -> interleaved pairs; else real-only.
    if ((long long)out_size >= 2LL * NCPLX) {
        k_cwt<false><<<dim3(NA_, BATCH), NTH>>>(Psih, (float*)d_out);
    } else {
        k_cwt<true><<<dim3(NA_, BATCH), NTH>>>(Psih, (float*)d_out);
    }
}